// round 11
// baseline (speedup 1.0000x reference)
#include <cuda_runtime.h>
#include <cuda_fp16.h>
#include <math.h>
#include <stdint.h>

#define HIDDEN 1024
#define FFN    2048
#define NE     8
#define NTOK   8192
#define TOTAL  (NTOK * 2)
#define NRBLK  (NTOK / 8)                    // router blocks (8 tokens each)

#define BM 128
#define BN 256
#define BK 32
#define STAGES 4

#define ASTR 40                              // halfs per A smem row (80B)
#define BSTR 264                             // halfs per B smem row (528B)
#define A_TILE_B (BM * ASTR * 2)             // 10240
#define B_TILE_B (BK * BSTR * 2)             // 16896
#define STAGE_B  (A_TILE_B + B_TILE_B)       // 27136
#define SMEM_B   (STAGES * STAGE_B)          // 108544

// ---------------- device scratch ----------------
__device__ int    g_pcnt[NRBLK * NE];
__device__ int    g_cnt[NE];
__device__ int    g_off[NE];
__device__ int    g_fill[NE];
__device__ int    g_te[NTOK * 2];
__device__ float  g_tw[NTOK * 2];
__device__ int    g_ent[TOTAL];
__device__ float  g_wt [TOTAL];
__device__ __half g_xh [(size_t)NTOK * HIDDEN];        // fp16 x
__device__ __half g_w1h[(size_t)NE * HIDDEN * FFN];    // fp16 W1
__device__ __half g_w2h[(size_t)NE * FFN * HIDDEN];    // fp16 W2
__device__ __half g_h  [(size_t)TOTAL * FFN];          // fp16 gelu(xW1+b1)
__device__ float  g_y  [(size_t)NTOK * 2 * HIDDEN];    // per-(token,k) expert output

// ---------------- helpers ----------------
__device__ __forceinline__ float gelu_exact(float v) {
    return 0.5f * v * (1.0f + erff(v * 0.7071067811865476f));
}
__device__ __forceinline__ unsigned smem_u32(const void* p) {
    return (unsigned)__cvta_generic_to_shared(p);
}
__device__ __forceinline__ void cpasync16(void* smem, const void* g, bool valid) {
    unsigned s = smem_u32(smem);
    int sz = valid ? 16 : 0;
    asm volatile("cp.async.cg.shared.global [%0], [%1], 16, %2;\n" :: "r"(s), "l"(g), "r"(sz));
}
__device__ __forceinline__ void cpcommit() { asm volatile("cp.async.commit_group;\n"); }
template<int N> __device__ __forceinline__ void cpwait() {
    asm volatile("cp.async.wait_group %0;\n" :: "n"(N));
}
__device__ __forceinline__ void ldsm4(unsigned r[4], unsigned addr) {
    asm volatile("ldmatrix.sync.aligned.m8n8.x4.shared.b16 {%0,%1,%2,%3}, [%4];"
                 : "=r"(r[0]), "=r"(r[1]), "=r"(r[2]), "=r"(r[3]) : "r"(addr));
}
__device__ __forceinline__ void ldsm4t(unsigned r[4], unsigned addr) {
    asm volatile("ldmatrix.sync.aligned.m8n8.x4.trans.shared.b16 {%0,%1,%2,%3}, [%4];"
                 : "=r"(r[0]), "=r"(r[1]), "=r"(r[2]), "=r"(r[3]) : "r"(addr));
}
__device__ __forceinline__ void mma16816(float c[4], const unsigned a[4], const unsigned b[2]) {
    asm volatile(
        "mma.sync.aligned.m16n8k16.row.col.f32.f16.f16.f32 "
        "{%0,%1,%2,%3}, {%4,%5,%6,%7}, {%8,%9}, {%0,%1,%2,%3};\n"
        : "+f"(c[0]), "+f"(c[1]), "+f"(c[2]), "+f"(c[3])
        : "r"(a[0]), "r"(a[1]), "r"(a[2]), "r"(a[3]), "r"(b[0]), "r"(b[1]));
}

// ---------------- small kernels ----------------
__global__ void cvt_half_kernel(const float4* __restrict__ src, uint2* __restrict__ dst, int n4) {
    int i = blockIdx.x * 256 + threadIdx.x;
    if (i < n4) {
        float4 v = src[i];
        __half2 a = __floats2half2_rn(v.x, v.y);
        __half2 b = __floats2half2_rn(v.z, v.w);
        dst[i] = make_uint2(*(unsigned*)&a, *(unsigned*)&b);
    }
}

// router (one warp per token); per-block expert histogram -> g_pcnt (no global atomics)
__global__ __launch_bounds__(256) void router_kernel(
    const float* __restrict__ x, const float* __restrict__ Wr, const float* __restrict__ br)
{
    __shared__ int bc[NE];
    const int warp = (blockIdx.x * blockDim.x + threadIdx.x) >> 5;
    const int lane = threadIdx.x & 31;
    const int tid = threadIdx.x;
    if (tid < NE) bc[tid] = 0;
    __syncthreads();

    const float* xr = x + (size_t)warp * HIDDEN;
    float s[NE];
#pragma unroll
    for (int e = 0; e < NE; e++) s[e] = 0.f;

    for (int h = lane; h < HIDDEN; h += 32) {
        float xv = xr[h];
        const float4* w4 = reinterpret_cast<const float4*>(Wr + (size_t)h * NE);
        float4 wa = w4[0], wb = w4[1];
        s[0] += xv * wa.x; s[1] += xv * wa.y; s[2] += xv * wa.z; s[3] += xv * wa.w;
        s[4] += xv * wb.x; s[5] += xv * wb.y; s[6] += xv * wb.z; s[7] += xv * wb.w;
    }
#pragma unroll
    for (int e = 0; e < NE; e++)
#pragma unroll
        for (int o = 16; o > 0; o >>= 1) s[e] += __shfl_xor_sync(0xffffffffu, s[e], o);

    if (lane == 0) {
        float l[NE], m = -1e30f;
#pragma unroll
        for (int e = 0; e < NE; e++) { l[e] = s[e] + br[e]; m = fmaxf(m, l[e]); }
        float p[NE], Z = 0.f;
#pragma unroll
        for (int e = 0; e < NE; e++) { p[e] = expf(l[e] - m); Z += p[e]; }
#pragma unroll
        for (int e = 0; e < NE; e++) p[e] /= Z;

        int i1 = 0; float v1 = p[0];
#pragma unroll
        for (int e = 1; e < NE; e++) if (p[e] > v1) { v1 = p[e]; i1 = e; }
        int i2 = -1; float v2 = -1.f;
#pragma unroll
        for (int e = 0; e < NE; e++) if (e != i1 && p[e] > v2) { v2 = p[e]; i2 = e; }

        float ex = expf(v2 - v1);
        float w1 = 1.f / (1.f + ex);
        float w2 = ex / (1.f + ex);

        g_te[2 * warp + 0] = i1;  g_tw[2 * warp + 0] = w1;
        g_te[2 * warp + 1] = i2;  g_tw[2 * warp + 1] = w2;
        atomicAdd(&bc[i1], 1);
        atomicAdd(&bc[i2], 1);
    }
    __syncthreads();
    if (tid < NE) g_pcnt[blockIdx.x * NE + tid] = bc[tid];
}

// reduce partial counts -> g_cnt, g_off; zero g_fill
__global__ __launch_bounds__(256) void scan_kernel() {
    __shared__ int part[256];
    const int tid = threadIdx.x;
    for (int e = 0; e < NE; e++) {
        int sum = 0;
        for (int i = tid; i < NRBLK; i += 256) sum += g_pcnt[i * NE + e];
        part[tid] = sum;
        __syncthreads();
        for (int o = 128; o > 0; o >>= 1) {
            if (tid < o) part[tid] += part[tid + o];
            __syncthreads();
        }
        if (tid == 0) g_cnt[e] = part[0];
        __syncthreads();
    }
    if (tid == 0) {
        int acc = 0;
        for (int e = 0; e < NE; e++) { g_off[e] = acc; acc += g_cnt[e]; g_fill[e] = 0; }
    }
}

__global__ void scatter_kernel() {
    int t = blockIdx.x * 256 + threadIdx.x;
    if (t >= NTOK) return;
    int   e1 = g_te[2 * t],     e2 = g_te[2 * t + 1];
    float w1 = g_tw[2 * t],     w2 = g_tw[2 * t + 1];
    int s1 = atomicAdd(&g_fill[e1], 1);
    int p1 = g_off[e1] + s1;
    g_ent[p1] = (t << 1);       g_wt[p1] = w1;
    int s2 = atomicAdd(&g_fill[e2], 1);
    int p2 = g_off[e2] + s2;
    g_ent[p2] = (t << 1) | 1;   g_wt[p2] = w2;
}

// ---------------- GEMM1 (per-expert): h = gelu(gather(x) @ W1[e] + b1[e]) ----------------
__global__ __launch_bounds__(256, 1) void gemm1_kernel(const float* __restrict__ b1, int e)
{
    const int rows = g_cnt[e];
    const int m0 = blockIdx.x * BM;
    if (m0 >= rows) return;
    const int off = g_off[e];
    const int n0 = blockIdx.y * BN;

    extern __shared__ __align__(128) char sa[];
    __shared__ int toks[BM];

    const int tid = threadIdx.x;
    const int wid = tid >> 5, lane = tid & 31;
    const int wm = (wid >> 2) * 64, wn = (wid & 3) * 64;

    if (tid < BM) {
        int r = m0 + tid;
        toks[tid] = (r < rows) ? (g_ent[off + r] >> 1) : -1;
    }
    __syncthreads();

    const __half* Wb = g_w1h + (size_t)e * HIDDEN * FFN;

#define LOAD1(ST, K0)                                                                    \
    do {                                                                                 \
        char* As_ = sa + (ST) * STAGE_B;                                                 \
        char* Bs_ = As_ + A_TILE_B;                                                      \
        _Pragma("unroll")                                                                \
        for (int i = 0; i < 2; i++) {                                                    \
            int f = tid + i * 256; int r = f >> 2, c = f & 3;                            \
            int tk = toks[r];                                                            \
            cpasync16(As_ + r * (ASTR * 2) + c * 16,                                     \
                      g_xh + (size_t)(tk < 0 ? 0 : tk) * HIDDEN + (K0) + c * 8,          \
                      tk >= 0);                                                          \
        }                                                                                \
        _Pragma("unroll")                                                                \
        for (int i = 0; i < 4; i++) {                                                    \
            int f = tid + i * 256; int r = f >> 5, c = f & 31;                           \
            cpasync16(Bs_ + r * (BSTR * 2) + c * 16,                                     \
                      Wb + (size_t)((K0) + r) * FFN + n0 + c * 8, true);                 \
        }                                                                                \
    } while (0)

    float c[4][8][4];
#pragma unroll
    for (int a = 0; a < 4; a++)
#pragma unroll
        for (int b = 0; b < 8; b++)
#pragma unroll
            for (int k = 0; k < 4; k++) c[a][b][k] = 0.f;

    const int KT = HIDDEN / BK;  // 32
    LOAD1(0, 0);        cpcommit();
    LOAD1(1, BK);       cpcommit();
    LOAD1(2, 2 * BK);   cpcommit();

    const int arow = (lane & 7) + ((lane >> 3) & 1) * 8;
    const int akoff = ((lane >> 4) & 1) * 8;
    const int brow_in = ((lane >> 3) & 1) * 8 + (lane & 7);
    const int bnoff = ((lane >> 4) & 1) * 8;

    for (int kt = 0; kt < KT; kt++) {
        cpwait<2>();
        __syncthreads();
        const int st = kt & (STAGES - 1);
        const char* As_ = sa + st * STAGE_B;
        const char* Bs_ = As_ + A_TILE_B;
        const unsigned abase = smem_u32(As_);
        const unsigned bbase = smem_u32(Bs_);
#pragma unroll
        for (int ks = 0; ks < 2; ks++) {
            const int k0h = ks * 16;
            unsigned afr[4][4];
#pragma unroll
            for (int mi = 0; mi < 4; mi++)
                ldsm4(afr[mi], abase + ((wm + mi * 16 + arow) * ASTR + k0h + akoff) * 2);
            unsigned bfr[8][2];
#pragma unroll
            for (int p = 0; p < 4; p++) {
                unsigned r4[4];
                ldsm4t(r4, bbase + ((k0h + brow_in) * BSTR + wn + p * 16 + bnoff) * 2);
                bfr[2 * p][0] = r4[0]; bfr[2 * p][1] = r4[1];
                bfr[2 * p + 1][0] = r4[2]; bfr[2 * p + 1][1] = r4[3];
            }
#pragma unroll
            for (int mi = 0; mi < 4; mi++)
#pragma unroll
                for (int ng = 0; ng < 8; ng++)
                    mma16816(c[mi][ng], afr[mi], bfr[ng]);
        }
        if (kt + 3 < KT) {
            int st2 = (kt + 3) & (STAGES - 1);
            LOAD1(st2, (kt + 3) * BK);
        }
        cpcommit();
    }
#undef LOAD1

    const float* b1e = b1 + (size_t)e * FFN;
#pragma unroll
    for (int mi = 0; mi < 4; mi++)
#pragma unroll
        for (int hh = 0; hh < 2; hh++) {
            int rl = wm + mi * 16 + (lane >> 2) + hh * 8;
            int r = m0 + rl;
            if (r < rows) {
                size_t base = (size_t)(off + r) * FFN + n0;
#pragma unroll
                for (int ng = 0; ng < 8; ng++) {
                    int col = wn + ng * 8 + 2 * (lane & 3);
                    float v0 = gelu_exact(c[mi][ng][hh * 2 + 0] + b1e[n0 + col]);
                    float v1 = gelu_exact(c[mi][ng][hh * 2 + 1] + b1e[n0 + col + 1]);
                    __half2 hv = __floats2half2_rn(v0, v1);
                    *reinterpret_cast<__half2*>(&g_h[base + col]) = hv;
                }
            }
        }
}

// ---------------- GEMM2 (per-expert): y[(token,k)] = w * (h @ W2[e] + b2[e]) ----------------
__global__ __launch_bounds__(256, 1) void gemm2_kernel(const float* __restrict__ b2, int e)
{
    const int rows = g_cnt[e];
    const int m0 = blockIdx.x * BM;
    if (m0 >= rows) return;
    const int off = g_off[e];
    const int n0 = blockIdx.y * BN;

    extern __shared__ __align__(128) char sa[];
    __shared__ int   ents[BM];
    __shared__ float wts[BM];

    const int tid = threadIdx.x;
    const int wid = tid >> 5, lane = tid & 31;
    const int wm = (wid >> 2) * 64, wn = (wid & 3) * 64;

    if (tid < BM) {
        int r = m0 + tid;
        ents[tid] = (r < rows) ? g_ent[off + r] : -1;
        wts [tid] = (r < rows) ? g_wt [off + r] : 0.f;
    }
    __syncthreads();

    const __half* Wb = g_w2h + (size_t)e * FFN * HIDDEN;

#define LOAD2(ST, K0)                                                                    \
    do {                                                                                 \
        char* As_ = sa + (ST) * STAGE_B;                                                 \
        char* Bs_ = As_ + A_TILE_B;                                                      \
        _Pragma("unroll")                                                                \
        for (int i = 0; i < 2; i++) {                                                    \
            int f = tid + i * 256; int r = f >> 2, c = f & 3;                            \
            bool valid = (m0 + r) < rows;                                                \
            cpasync16(As_ + r * (ASTR * 2) + c * 16,                                     \
                      g_h + (size_t)(valid ? (off + m0 + r) : 0) * FFN + (K0) + c * 8,   \
                      valid);                                                            \
        }                                                                                \
        _Pragma("unroll")                                                                \
        for (int i = 0; i < 4; i++) {                                                    \
            int f = tid + i * 256; int r = f >> 5, c = f & 31;                           \
            cpasync16(Bs_ + r * (BSTR * 2) + c * 16,                                     \
                      Wb + (size_t)((K0) + r) * HIDDEN + n0 + c * 8, true);              \
        }                                                                                \
    } while (0)

    float c[4][8][4];
#pragma unroll
    for (int a = 0; a < 4; a++)
#pragma unroll
        for (int b = 0; b < 8; b++)
#pragma unroll
            for (int k = 0; k < 4; k++) c[a][b][k] = 0.f;

    const int KT = FFN / BK;  // 64
    LOAD2(0, 0);        cpcommit();
    LOAD2(1, BK);       cpcommit();
    LOAD2(2, 2 * BK);   cpcommit();

    const int arow = (lane & 7) + ((lane >> 3) & 1) * 8;
    const int akoff = ((lane >> 4) & 1) * 8;
    const int brow_in = ((lane >> 3) & 1) * 8 + (lane & 7);
    const int bnoff = ((lane >> 4) & 1) * 8;

    for (int kt = 0; kt < KT; kt++) {
        cpwait<2>();
        __syncthreads();
        const int st = kt & (STAGES - 1);
        const char* As_ = sa + st * STAGE_B;
        const char* Bs_ = As_ + A_TILE_B;
        const unsigned abase = smem_u32(As_);
        const unsigned bbase = smem_u32(Bs_);
#pragma unroll
        for (int ks = 0; ks < 2; ks++) {
            const int k0h = ks * 16;
            unsigned afr[4][4];
#pragma unroll
            for (int mi = 0; mi < 4; mi++)
                ldsm4(afr[mi], abase + ((wm + mi * 16 + arow) * ASTR + k0h + akoff) * 2);
            unsigned bfr[8][2];
#pragma unroll
            for (int p = 0; p < 4; p++) {
                unsigned r4[4];
                ldsm4t(r4, bbase + ((k0h + brow_in) * BSTR + wn + p * 16 + bnoff) * 2);
                bfr[2 * p][0] = r4[0]; bfr[2 * p][1] = r4[1];
                bfr[2 * p + 1][0] = r4[2]; bfr[2 * p + 1][1] = r4[3];
            }
#pragma unroll
            for (int mi = 0; mi < 4; mi++)
#pragma unroll
                for (int ng = 0; ng < 8; ng++)
                    mma16816(c[mi][ng], afr[mi], bfr[ng]);
        }
        if (kt + 3 < KT) {
            int st2 = (kt + 3) & (STAGES - 1);
            LOAD2(st2, (kt + 3) * BK);
        }
        cpcommit();
    }
#undef LOAD2

    const float* b2e = b2 + (size_t)e * HIDDEN;
#pragma unroll
    for (int mi = 0; mi < 4; mi++)
#pragma unroll
        for (int hh = 0; hh < 2; hh++) {
            int rl = wm + mi * 16 + (lane >> 2) + hh * 8;
            int en = ents[rl];
            if (en >= 0) {
                int tok = en >> 1, kk = en & 1;
                float w = wts[rl];
                size_t base = ((size_t)tok * 2 + kk) * HIDDEN + n0;
#pragma unroll
                for (int ng = 0; ng < 8; ng++) {
                    int col = wn + ng * 8 + 2 * (lane & 3);
                    float v0 = w * (c[mi][ng][hh * 2 + 0] + b2e[n0 + col]);
                    float v1 = w * (c[mi][ng][hh * 2 + 1] + b2e[n0 + col + 1]);
                    *reinterpret_cast<float2*>(&g_y[base + col]) = make_float2(v0, v1);
                }
            }
        }
}

// ---------------- combine ----------------
__global__ void combine_kernel(float4* __restrict__ out) {
    int i = blockIdx.x * 256 + threadIdx.x;
    const float4* y4 = reinterpret_cast<const float4*>(g_y);
    int t = i >> 8, cc = i & 255;
    float4 a = y4[((size_t)t * 2) * 256 + cc];
    float4 b = y4[((size_t)t * 2 + 1) * 256 + cc];
    out[i] = make_float4(a.x + b.x, a.y + b.y, a.z + b.z, a.w + b.w);
}

// ---------------- launch (graph: forked cvt + per-expert pipelined GEMMs) ----------------
extern "C" void kernel_launch(void* const* d_in, const int* in_sizes, int n_in,
                              void* d_out, int out_size)
{
    const float* x  = (const float*)d_in[0];
    const float* Wr = (const float*)d_in[1];
    const float* br = (const float*)d_in[2];
    const float* W1 = (const float*)d_in[3];
    const float* b1 = (const float*)d_in[4];
    const float* W2 = (const float*)d_in[5];
    const float* b2 = (const float*)d_in[6];
    float* out = (float*)d_out;

    static cudaStream_t s1 = nullptr, s2 = nullptr;
    static cudaEvent_t evA = nullptr, ev1 = nullptr, ev2 = nullptr, evS = nullptr,
                       evF1 = nullptr, evF2 = nullptr;
    if (s1 == nullptr) {
        cudaStreamCreateWithFlags(&s1, cudaStreamNonBlocking);
        cudaStreamCreateWithFlags(&s2, cudaStreamNonBlocking);
        cudaEventCreateWithFlags(&evA, cudaEventDisableTiming);
        cudaEventCreateWithFlags(&ev1, cudaEventDisableTiming);
        cudaEventCreateWithFlags(&ev2, cudaEventDisableTiming);
        cudaEventCreateWithFlags(&evS, cudaEventDisableTiming);
        cudaEventCreateWithFlags(&evF1, cudaEventDisableTiming);
        cudaEventCreateWithFlags(&evF2, cudaEventDisableTiming);
        cudaFuncSetAttribute(gemm1_kernel, cudaFuncAttributeMaxDynamicSharedMemorySize, SMEM_B);
        cudaFuncSetAttribute(gemm2_kernel, cudaFuncAttributeMaxDynamicSharedMemorySize, SMEM_B);
    }

    __half* xh_p  = nullptr; cudaGetSymbolAddress((void**)&xh_p,  g_xh);
    __half* w1h_p = nullptr; cudaGetSymbolAddress((void**)&w1h_p, g_w1h);
    __half* w2h_p = nullptr; cudaGetSymbolAddress((void**)&w2h_p, g_w2h);

    // fork side branches
    cudaEventRecord(evA, 0);
    cudaStreamWaitEvent(s1, evA, 0);
    cudaStreamWaitEvent(s2, evA, 0);

    // s1: x + W1 conversion
    cvt_half_kernel<<<(NTOK * HIDDEN / 4) / 256, 256, 0, s1>>>(
        (const float4*)x, (uint2*)xh_p, NTOK * HIDDEN / 4);
    cvt_half_kernel<<<(NE * HIDDEN * FFN / 4) / 256, 256, 0, s1>>>(
        (const float4*)W1, (uint2*)w1h_p, NE * HIDDEN * FFN / 4);
    cudaEventRecord(ev1, s1);

    // s2: W2 conversion
    cvt_half_kernel<<<(NE * FFN * HIDDEN / 4) / 256, 256, 0, s2>>>(
        (const float4*)W2, (uint2*)w2h_p, NE * FFN * HIDDEN / 4);
    cudaEventRecord(ev2, s2);

    // main: routing chain (no zero kernel; router emits per-block histograms)
    router_kernel<<<NRBLK, 256>>>(x, Wr, br);
    scan_kernel<<<1, 256>>>();
    scatter_kernel<<<NTOK / 256, 256>>>();
    cudaEventRecord(evS, 0);

    const dim3 g1grid(NTOK / BM, FFN / BN);      // 64 x 8 (early-exit beyond rows)
    const dim3 g2grid(NTOK / BM, HIDDEN / BN);   // 64 x 4

    // s1: even experts  g1(e) -> g2(e), pipelined against s2's odd experts
    cudaStreamWaitEvent(s1, evS, 0);
    cudaStreamWaitEvent(s1, ev2, 0);             // s1's gemm2 needs W2
    // s2: odd experts
    cudaStreamWaitEvent(s2, evS, 0);
    cudaStreamWaitEvent(s2, ev1, 0);             // s2's gemms need x/W1

    for (int e = 0; e < NE; e += 2) {
        gemm1_kernel<<<g1grid, 256, SMEM_B, s1>>>(b1, e);
        gemm1_kernel<<<g1grid, 256, SMEM_B, s2>>>(b1, e + 1);
        gemm2_kernel<<<g2grid, 256, SMEM_B, s1>>>(b2, e);
        gemm2_kernel<<<g2grid, 256, SMEM_B, s2>>>(b2, e + 1);
    }
    cudaEventRecord(evF1, s1);
    cudaEventRecord(evF2, s2);

    // join and combine on main stream
    cudaStreamWaitEvent(0, evF1, 0);
    cudaStreamWaitEvent(0, evF2, 0);
    combine_kernel<<<(NTOK * HIDDEN / 4) / 256, 256>>>(reinterpret_cast<float4*>(out));
}

// round 12
// speedup vs baseline: 1.0747x; 1.0747x over previous
#include <cuda_runtime.h>
#include <cuda_fp16.h>
#include <math.h>
#include <stdint.h>

#define HIDDEN 1024
#define FFN    2048
#define NE     8
#define NTOK   8192
#define TOTAL  (NTOK * 2)
#define NRBLK  (NTOK / 8)                    // router blocks (8 tokens each)

#define BM 128
#define BN 256
#define BK 32
#define STAGES 4

#define ASTR 40                              // halfs per A smem row (80B)
#define BSTR 264                             // halfs per B smem row (528B)
#define A_TILE_B (BM * ASTR * 2)             // 10240
#define B_TILE_B (BK * BSTR * 2)             // 16896
#define STAGE_B  (A_TILE_B + B_TILE_B)       // 27136
#define SMEM_B   (STAGES * STAGE_B)          // 108544

// ---------------- device scratch ----------------
__device__ int    g_pcnt[NRBLK * NE];
__device__ int    g_cnt[NE];
__device__ int    g_off[NE];
__device__ int    g_fill[NE];
__device__ int    g_te[NTOK * 2];
__device__ float  g_tw[NTOK * 2];
__device__ int    g_ent[TOTAL];
__device__ float  g_wt [TOTAL];
__device__ __half g_xh [(size_t)NTOK * HIDDEN];        // fp16 x
__device__ __half g_w1h[(size_t)NE * HIDDEN * FFN];    // fp16 W1
__device__ __half g_w2h[(size_t)NE * FFN * HIDDEN];    // fp16 W2
__device__ __half g_h  [(size_t)TOTAL * FFN];          // fp16 gelu(xW1+b1)
__device__ float  g_y  [(size_t)NTOK * 2 * HIDDEN];    // per-(token,k) expert output

// ---------------- helpers ----------------
__device__ __forceinline__ float gelu_exact(float v) {
    return 0.5f * v * (1.0f + erff(v * 0.7071067811865476f));
}
__device__ __forceinline__ unsigned smem_u32(const void* p) {
    return (unsigned)__cvta_generic_to_shared(p);
}
__device__ __forceinline__ void cpasync16(void* smem, const void* g, bool valid) {
    unsigned s = smem_u32(smem);
    int sz = valid ? 16 : 0;
    asm volatile("cp.async.cg.shared.global [%0], [%1], 16, %2;\n" :: "r"(s), "l"(g), "r"(sz));
}
__device__ __forceinline__ void cpcommit() { asm volatile("cp.async.commit_group;\n"); }
template<int N> __device__ __forceinline__ void cpwait() {
    asm volatile("cp.async.wait_group %0;\n" :: "n"(N));
}
__device__ __forceinline__ void ldsm4(unsigned r[4], unsigned addr) {
    asm volatile("ldmatrix.sync.aligned.m8n8.x4.shared.b16 {%0,%1,%2,%3}, [%4];"
                 : "=r"(r[0]), "=r"(r[1]), "=r"(r[2]), "=r"(r[3]) : "r"(addr));
}
__device__ __forceinline__ void ldsm4t(unsigned r[4], unsigned addr) {
    asm volatile("ldmatrix.sync.aligned.m8n8.x4.trans.shared.b16 {%0,%1,%2,%3}, [%4];"
                 : "=r"(r[0]), "=r"(r[1]), "=r"(r[2]), "=r"(r[3]) : "r"(addr));
}
__device__ __forceinline__ void mma16816(float c[4], const unsigned a[4], const unsigned b[2]) {
    asm volatile(
        "mma.sync.aligned.m16n8k16.row.col.f32.f16.f16.f32 "
        "{%0,%1,%2,%3}, {%4,%5,%6,%7}, {%8,%9}, {%0,%1,%2,%3};\n"
        : "+f"(c[0]), "+f"(c[1]), "+f"(c[2]), "+f"(c[3])
        : "r"(a[0]), "r"(a[1]), "r"(a[2]), "r"(a[3]), "r"(b[0]), "r"(b[1]));
}

// ---------------- small kernels ----------------
__global__ void cvt_half_kernel(const float4* __restrict__ src, uint2* __restrict__ dst, int n4) {
    int i = blockIdx.x * 256 + threadIdx.x;
    if (i < n4) {
        float4 v = src[i];
        __half2 a = __floats2half2_rn(v.x, v.y);
        __half2 b = __floats2half2_rn(v.z, v.w);
        dst[i] = make_uint2(*(unsigned*)&a, *(unsigned*)&b);
    }
}

// router (one warp per token); per-block expert histogram -> g_pcnt (no global atomics)
__global__ __launch_bounds__(256) void router_kernel(
    const float* __restrict__ x, const float* __restrict__ Wr, const float* __restrict__ br)
{
    __shared__ int bc[NE];
    const int warp = (blockIdx.x * blockDim.x + threadIdx.x) >> 5;
    const int lane = threadIdx.x & 31;
    const int tid = threadIdx.x;
    if (tid < NE) bc[tid] = 0;
    __syncthreads();

    const float* xr = x + (size_t)warp * HIDDEN;
    float s[NE];
#pragma unroll
    for (int e = 0; e < NE; e++) s[e] = 0.f;

    for (int h = lane; h < HIDDEN; h += 32) {
        float xv = xr[h];
        const float4* w4 = reinterpret_cast<const float4*>(Wr + (size_t)h * NE);
        float4 wa = w4[0], wb = w4[1];
        s[0] += xv * wa.x; s[1] += xv * wa.y; s[2] += xv * wa.z; s[3] += xv * wa.w;
        s[4] += xv * wb.x; s[5] += xv * wb.y; s[6] += xv * wb.z; s[7] += xv * wb.w;
    }
#pragma unroll
    for (int e = 0; e < NE; e++)
#pragma unroll
        for (int o = 16; o > 0; o >>= 1) s[e] += __shfl_xor_sync(0xffffffffu, s[e], o);

    if (lane == 0) {
        float l[NE], m = -1e30f;
#pragma unroll
        for (int e = 0; e < NE; e++) { l[e] = s[e] + br[e]; m = fmaxf(m, l[e]); }
        float p[NE], Z = 0.f;
#pragma unroll
        for (int e = 0; e < NE; e++) { p[e] = expf(l[e] - m); Z += p[e]; }
#pragma unroll
        for (int e = 0; e < NE; e++) p[e] /= Z;

        int i1 = 0; float v1 = p[0];
#pragma unroll
        for (int e = 1; e < NE; e++) if (p[e] > v1) { v1 = p[e]; i1 = e; }
        int i2 = -1; float v2 = -1.f;
#pragma unroll
        for (int e = 0; e < NE; e++) if (e != i1 && p[e] > v2) { v2 = p[e]; i2 = e; }

        float ex = expf(v2 - v1);
        float w1 = 1.f / (1.f + ex);
        float w2 = ex / (1.f + ex);

        g_te[2 * warp + 0] = i1;  g_tw[2 * warp + 0] = w1;
        g_te[2 * warp + 1] = i2;  g_tw[2 * warp + 1] = w2;
        atomicAdd(&bc[i1], 1);
        atomicAdd(&bc[i2], 1);
    }
    __syncthreads();
    if (tid < NE) g_pcnt[blockIdx.x * NE + tid] = bc[tid];
}

// reduce partial counts -> g_cnt, g_off; zero g_fill
__global__ __launch_bounds__(256) void scan_kernel() {
    __shared__ int part[256];
    const int tid = threadIdx.x;
    for (int e = 0; e < NE; e++) {
        int sum = 0;
        for (int i = tid; i < NRBLK; i += 256) sum += g_pcnt[i * NE + e];
        part[tid] = sum;
        __syncthreads();
        for (int o = 128; o > 0; o >>= 1) {
            if (tid < o) part[tid] += part[tid + o];
            __syncthreads();
        }
        if (tid == 0) g_cnt[e] = part[0];
        __syncthreads();
    }
    if (tid == 0) {
        int acc = 0;
        for (int e = 0; e < NE; e++) { g_off[e] = acc; acc += g_cnt[e]; g_fill[e] = 0; }
    }
}

__global__ void scatter_kernel() {
    int t = blockIdx.x * 256 + threadIdx.x;
    if (t >= NTOK) return;
    int   e1 = g_te[2 * t],     e2 = g_te[2 * t + 1];
    float w1 = g_tw[2 * t],     w2 = g_tw[2 * t + 1];
    int s1 = atomicAdd(&g_fill[e1], 1);
    int p1 = g_off[e1] + s1;
    g_ent[p1] = (t << 1);       g_wt[p1] = w1;
    int s2 = atomicAdd(&g_fill[e2], 1);
    int p2 = g_off[e2] + s2;
    g_ent[p2] = (t << 1) | 1;   g_wt[p2] = w2;
}

// ---------------- GEMM1: h = gelu(gather(x) @ W1[e] + b1[e]) ----------------
__global__ __launch_bounds__(256, 1) void gemm1_kernel(const float* __restrict__ b1)
{
    const int e = blockIdx.z;
    const int rows = g_cnt[e];
    const int m0 = blockIdx.x * BM;
    if (m0 >= rows) return;
    const int off = g_off[e];
    const int n0 = blockIdx.y * BN;

    extern __shared__ __align__(128) char sa[];
    __shared__ int toks[BM];

    const int tid = threadIdx.x;
    const int wid = tid >> 5, lane = tid & 31;
    const int wm = (wid >> 2) * 64, wn = (wid & 3) * 64;

    if (tid < BM) {
        int r = m0 + tid;
        toks[tid] = (r < rows) ? (g_ent[off + r] >> 1) : -1;
    }
    __syncthreads();

    const __half* Wb = g_w1h + (size_t)e * HIDDEN * FFN;

#define LOAD1(ST, K0)                                                                    \
    do {                                                                                 \
        char* As_ = sa + (ST) * STAGE_B;                                                 \
        char* Bs_ = As_ + A_TILE_B;                                                      \
        _Pragma("unroll")                                                                \
        for (int i = 0; i < 2; i++) {                                                    \
            int f = tid + i * 256; int r = f >> 2, c = f & 3;                            \
            int tk = toks[r];                                                            \
            cpasync16(As_ + r * (ASTR * 2) + c * 16,                                     \
                      g_xh + (size_t)(tk < 0 ? 0 : tk) * HIDDEN + (K0) + c * 8,          \
                      tk >= 0);                                                          \
        }                                                                                \
        _Pragma("unroll")                                                                \
        for (int i = 0; i < 4; i++) {                                                    \
            int f = tid + i * 256; int r = f >> 5, c = f & 31;                           \
            cpasync16(Bs_ + r * (BSTR * 2) + c * 16,                                     \
                      Wb + (size_t)((K0) + r) * FFN + n0 + c * 8, true);                 \
        }                                                                                \
    } while (0)

    float c[4][8][4];
#pragma unroll
    for (int a = 0; a < 4; a++)
#pragma unroll
        for (int b = 0; b < 8; b++)
#pragma unroll
            for (int k = 0; k < 4; k++) c[a][b][k] = 0.f;

    const int KT = HIDDEN / BK;  // 32
    LOAD1(0, 0);        cpcommit();
    LOAD1(1, BK);       cpcommit();
    LOAD1(2, 2 * BK);   cpcommit();

    const int arow = (lane & 7) + ((lane >> 3) & 1) * 8;
    const int akoff = ((lane >> 4) & 1) * 8;
    const int brow_in = ((lane >> 3) & 1) * 8 + (lane & 7);
    const int bnoff = ((lane >> 4) & 1) * 8;

    for (int kt = 0; kt < KT; kt++) {
        cpwait<2>();
        __syncthreads();
        const int st = kt & (STAGES - 1);
        const char* As_ = sa + st * STAGE_B;
        const char* Bs_ = As_ + A_TILE_B;
        const unsigned abase = smem_u32(As_);
        const unsigned bbase = smem_u32(Bs_);
#pragma unroll
        for (int ks = 0; ks < 2; ks++) {
            const int k0h = ks * 16;
            unsigned afr[4][4];
#pragma unroll
            for (int mi = 0; mi < 4; mi++)
                ldsm4(afr[mi], abase + ((wm + mi * 16 + arow) * ASTR + k0h + akoff) * 2);
            unsigned bfr[8][2];
#pragma unroll
            for (int p = 0; p < 4; p++) {
                unsigned r4[4];
                ldsm4t(r4, bbase + ((k0h + brow_in) * BSTR + wn + p * 16 + bnoff) * 2);
                bfr[2 * p][0] = r4[0]; bfr[2 * p][1] = r4[1];
                bfr[2 * p + 1][0] = r4[2]; bfr[2 * p + 1][1] = r4[3];
            }
#pragma unroll
            for (int mi = 0; mi < 4; mi++)
#pragma unroll
                for (int ng = 0; ng < 8; ng++)
                    mma16816(c[mi][ng], afr[mi], bfr[ng]);
        }
        if (kt + 3 < KT) {
            int st2 = (kt + 3) & (STAGES - 1);
            LOAD1(st2, (kt + 3) * BK);
        }
        cpcommit();
    }
#undef LOAD1

    const float* b1e = b1 + (size_t)e * FFN;
#pragma unroll
    for (int mi = 0; mi < 4; mi++)
#pragma unroll
        for (int hh = 0; hh < 2; hh++) {
            int rl = wm + mi * 16 + (lane >> 2) + hh * 8;
            int r = m0 + rl;
            if (r < rows) {
                size_t base = (size_t)(off + r) * FFN + n0;
#pragma unroll
                for (int ng = 0; ng < 8; ng++) {
                    int col = wn + ng * 8 + 2 * (lane & 3);
                    float v0 = gelu_exact(c[mi][ng][hh * 2 + 0] + b1e[n0 + col]);
                    float v1 = gelu_exact(c[mi][ng][hh * 2 + 1] + b1e[n0 + col + 1]);
                    __half2 hv = __floats2half2_rn(v0, v1);
                    *reinterpret_cast<__half2*>(&g_h[base + col]) = hv;
                }
            }
        }
}

// ---------------- GEMM2: y[(token,k)] = w * (h @ W2[e] + b2[e]) ----------------
__global__ __launch_bounds__(256, 1) void gemm2_kernel(const float* __restrict__ b2)
{
    const int e = blockIdx.z;
    const int rows = g_cnt[e];
    const int m0 = blockIdx.x * BM;
    if (m0 >= rows) return;
    const int off = g_off[e];
    const int n0 = blockIdx.y * BN;

    extern __shared__ __align__(128) char sa[];
    __shared__ int   ents[BM];
    __shared__ float wts[BM];

    const int tid = threadIdx.x;
    const int wid = tid >> 5, lane = tid & 31;
    const int wm = (wid >> 2) * 64, wn = (wid & 3) * 64;

    if (tid < BM) {
        int r = m0 + tid;
        ents[tid] = (r < rows) ? g_ent[off + r] : -1;
        wts [tid] = (r < rows) ? g_wt [off + r] : 0.f;
    }
    __syncthreads();

    const __half* Wb = g_w2h + (size_t)e * FFN * HIDDEN;

#define LOAD2(ST, K0)                                                                    \
    do {                                                                                 \
        char* As_ = sa + (ST) * STAGE_B;                                                 \
        char* Bs_ = As_ + A_TILE_B;                                                      \
        _Pragma("unroll")                                                                \
        for (int i = 0; i < 2; i++) {                                                    \
            int f = tid + i * 256; int r = f >> 2, c = f & 3;                            \
            bool valid = (m0 + r) < rows;                                                \
            cpasync16(As_ + r * (ASTR * 2) + c * 16,                                     \
                      g_h + (size_t)(valid ? (off + m0 + r) : 0) * FFN + (K0) + c * 8,   \
                      valid);                                                            \
        }                                                                                \
        _Pragma("unroll")                                                                \
        for (int i = 0; i < 4; i++) {                                                    \
            int f = tid + i * 256; int r = f >> 5, c = f & 31;                           \
            cpasync16(Bs_ + r * (BSTR * 2) + c * 16,                                     \
                      Wb + (size_t)((K0) + r) * HIDDEN + n0 + c * 8, true);              \
        }                                                                                \
    } while (0)

    float c[4][8][4];
#pragma unroll
    for (int a = 0; a < 4; a++)
#pragma unroll
        for (int b = 0; b < 8; b++)
#pragma unroll
            for (int k = 0; k < 4; k++) c[a][b][k] = 0.f;

    const int KT = FFN / BK;  // 64
    LOAD2(0, 0);        cpcommit();
    LOAD2(1, BK);       cpcommit();
    LOAD2(2, 2 * BK);   cpcommit();

    const int arow = (lane & 7) + ((lane >> 3) & 1) * 8;
    const int akoff = ((lane >> 4) & 1) * 8;
    const int brow_in = ((lane >> 3) & 1) * 8 + (lane & 7);
    const int bnoff = ((lane >> 4) & 1) * 8;

    for (int kt = 0; kt < KT; kt++) {
        cpwait<2>();
        __syncthreads();
        const int st = kt & (STAGES - 1);
        const char* As_ = sa + st * STAGE_B;
        const char* Bs_ = As_ + A_TILE_B;
        const unsigned abase = smem_u32(As_);
        const unsigned bbase = smem_u32(Bs_);
#pragma unroll
        for (int ks = 0; ks < 2; ks++) {
            const int k0h = ks * 16;
            unsigned afr[4][4];
#pragma unroll
            for (int mi = 0; mi < 4; mi++)
                ldsm4(afr[mi], abase + ((wm + mi * 16 + arow) * ASTR + k0h + akoff) * 2);
            unsigned bfr[8][2];
#pragma unroll
            for (int p = 0; p < 4; p++) {
                unsigned r4[4];
                ldsm4t(r4, bbase + ((k0h + brow_in) * BSTR + wn + p * 16 + bnoff) * 2);
                bfr[2 * p][0] = r4[0]; bfr[2 * p][1] = r4[1];
                bfr[2 * p + 1][0] = r4[2]; bfr[2 * p + 1][1] = r4[3];
            }
#pragma unroll
            for (int mi = 0; mi < 4; mi++)
#pragma unroll
                for (int ng = 0; ng < 8; ng++)
                    mma16816(c[mi][ng], afr[mi], bfr[ng]);
        }
        if (kt + 3 < KT) {
            int st2 = (kt + 3) & (STAGES - 1);
            LOAD2(st2, (kt + 3) * BK);
        }
        cpcommit();
    }
#undef LOAD2

    const float* b2e = b2 + (size_t)e * HIDDEN;
#pragma unroll
    for (int mi = 0; mi < 4; mi++)
#pragma unroll
        for (int hh = 0; hh < 2; hh++) {
            int rl = wm + mi * 16 + (lane >> 2) + hh * 8;
            int en = ents[rl];
            if (en >= 0) {
                int tok = en >> 1, kk = en & 1;
                float w = wts[rl];
                size_t base = ((size_t)tok * 2 + kk) * HIDDEN + n0;
#pragma unroll
                for (int ng = 0; ng < 8; ng++) {
                    int col = wn + ng * 8 + 2 * (lane & 3);
                    float v0 = w * (c[mi][ng][hh * 2 + 0] + b2e[n0 + col]);
                    float v1 = w * (c[mi][ng][hh * 2 + 1] + b2e[n0 + col + 1]);
                    *reinterpret_cast<float2*>(&g_y[base + col]) = make_float2(v0, v1);
                }
            }
        }
}

// ---------------- combine ----------------
__global__ void combine_kernel(float4* __restrict__ out) {
    int i = blockIdx.x * 256 + threadIdx.x;
    const float4* y4 = reinterpret_cast<const float4*>(g_y);
    int t = i >> 8, cc = i & 255;
    float4 a = y4[((size_t)t * 2) * 256 + cc];
    float4 b = y4[((size_t)t * 2 + 1) * 256 + cc];
    out[i] = make_float4(a.x + b.x, a.y + b.y, a.z + b.z, a.w + b.w);
}

// ---------------- launch (graph has parallel branches via fork/join) ----------------
extern "C" void kernel_launch(void* const* d_in, const int* in_sizes, int n_in,
                              void* d_out, int out_size)
{
    const float* x  = (const float*)d_in[0];
    const float* Wr = (const float*)d_in[1];
    const float* br = (const float*)d_in[2];
    const float* W1 = (const float*)d_in[3];
    const float* b1 = (const float*)d_in[4];
    const float* W2 = (const float*)d_in[5];
    const float* b2 = (const float*)d_in[6];
    float* out = (float*)d_out;

    static cudaStream_t s1 = nullptr, s2 = nullptr;
    static cudaEvent_t evA = nullptr, ev1 = nullptr, ev2 = nullptr;
    if (s1 == nullptr) {
        cudaStreamCreateWithFlags(&s1, cudaStreamNonBlocking);
        cudaStreamCreateWithFlags(&s2, cudaStreamNonBlocking);
        cudaEventCreateWithFlags(&evA, cudaEventDisableTiming);
        cudaEventCreateWithFlags(&ev1, cudaEventDisableTiming);
        cudaEventCreateWithFlags(&ev2, cudaEventDisableTiming);
        cudaFuncSetAttribute(gemm1_kernel, cudaFuncAttributeMaxDynamicSharedMemorySize, SMEM_B);
        cudaFuncSetAttribute(gemm2_kernel, cudaFuncAttributeMaxDynamicSharedMemorySize, SMEM_B);
    }

    __half* xh_p  = nullptr; cudaGetSymbolAddress((void**)&xh_p,  g_xh);
    __half* w1h_p = nullptr; cudaGetSymbolAddress((void**)&w1h_p, g_w1h);
    __half* w2h_p = nullptr; cudaGetSymbolAddress((void**)&w2h_p, g_w2h);

    // fork side branches from the main (capturing) stream
    cudaEventRecord(evA, 0);
    cudaStreamWaitEvent(s1, evA, 0);
    cudaStreamWaitEvent(s2, evA, 0);

    // branch s1: x and W1 fp16 conversion (needed by gemm1)
    cvt_half_kernel<<<(NTOK * HIDDEN / 4) / 256, 256, 0, s1>>>(
        (const float4*)x, (uint2*)xh_p, NTOK * HIDDEN / 4);
    cvt_half_kernel<<<(NE * HIDDEN * FFN / 4) / 256, 256, 0, s1>>>(
        (const float4*)W1, (uint2*)w1h_p, NE * HIDDEN * FFN / 4);
    cudaEventRecord(ev1, s1);

    // branch s2: W2 conversion (needed only by gemm2; hides under router chain + gemm1)
    cvt_half_kernel<<<(NE * FFN * HIDDEN / 4) / 256, 256, 0, s2>>>(
        (const float4*)W2, (uint2*)w2h_p, NE * FFN * HIDDEN / 4);
    cudaEventRecord(ev2, s2);

    // main branch: routing chain (histogram router, no zero kernel)
    router_kernel<<<NRBLK, 256>>>(x, Wr, br);
    scan_kernel<<<1, 256>>>();
    scatter_kernel<<<NTOK / 256, 256>>>();

    // join s1 (x/W1 ready) then run gemm1
    cudaStreamWaitEvent(0, ev1, 0);
    gemm1_kernel<<<dim3(NTOK / BM, FFN / BN, NE), 256, SMEM_B>>>(b1);

    // join s2 (W2 ready) then gemm2 + combine
    cudaStreamWaitEvent(0, ev2, 0);
    gemm2_kernel<<<dim3(NTOK / BM, HIDDEN / BN, NE), 256, SMEM_B>>>(b2);
    combine_kernel<<<(NTOK * HIDDEN / 4) / 256, 256>>>(reinterpret_cast<float4*>(out));
}

// round 13
// speedup vs baseline: 1.0828x; 1.0075x over previous
#include <cuda_runtime.h>
#include <cuda_fp16.h>
#include <math.h>
#include <stdint.h>

#define HIDDEN 1024
#define FFN    2048
#define NE     8
#define NTOK   8192
#define TOTAL  (NTOK * 2)
#define NRBLK  (NTOK / 8)                    // router blocks (8 tokens each)

#define BM 128
#define BN 256
#define BK 32
#define STAGES 4

#define ASTR 40                              // halfs per A smem row (80B)
#define BSTR 264                             // halfs per B smem row (528B)
#define A_TILE_B (BM * ASTR * 2)             // 10240
#define B_TILE_B (BK * BSTR * 2)             // 16896
#define STAGE_B  (A_TILE_B + B_TILE_B)       // 27136
#define SMEM_B   (STAGES * STAGE_B)          // 108544

// ---------------- device scratch ----------------
__device__ int    g_pcnt[NRBLK * NE];
__device__ int    g_cnt[NE];
__device__ int    g_off[NE];
__device__ int    g_fill[NE];
__device__ int    g_te[NTOK * 2];
__device__ float  g_tw[NTOK * 2];
__device__ int    g_ent[TOTAL];
__device__ float  g_wt [TOTAL];
__device__ __half g_xh [(size_t)NTOK * HIDDEN];        // fp16 x
__device__ __half g_w1h[(size_t)NE * HIDDEN * FFN];    // fp16 W1
__device__ __half g_w2h[(size_t)NE * FFN * HIDDEN];    // fp16 W2
__device__ __half g_h  [(size_t)TOTAL * FFN];          // fp16 gelu(xW1+b1)
__device__ __half g_y  [(size_t)NTOK * 2 * HIDDEN];    // fp16 per-(token,k) expert output

// ---------------- helpers ----------------
__device__ __forceinline__ float gelu_exact(float v) {
    return 0.5f * v * (1.0f + erff(v * 0.7071067811865476f));
}
__device__ __forceinline__ unsigned smem_u32(const void* p) {
    return (unsigned)__cvta_generic_to_shared(p);
}
__device__ __forceinline__ void cpasync16(void* smem, const void* g, bool valid) {
    unsigned s = smem_u32(smem);
    int sz = valid ? 16 : 0;
    asm volatile("cp.async.cg.shared.global [%0], [%1], 16, %2;\n" :: "r"(s), "l"(g), "r"(sz));
}
__device__ __forceinline__ void cpcommit() { asm volatile("cp.async.commit_group;\n"); }
template<int N> __device__ __forceinline__ void cpwait() {
    asm volatile("cp.async.wait_group %0;\n" :: "n"(N));
}
__device__ __forceinline__ void ldsm4(unsigned r[4], unsigned addr) {
    asm volatile("ldmatrix.sync.aligned.m8n8.x4.shared.b16 {%0,%1,%2,%3}, [%4];"
                 : "=r"(r[0]), "=r"(r[1]), "=r"(r[2]), "=r"(r[3]) : "r"(addr));
}
__device__ __forceinline__ void ldsm4t(unsigned r[4], unsigned addr) {
    asm volatile("ldmatrix.sync.aligned.m8n8.x4.trans.shared.b16 {%0,%1,%2,%3}, [%4];"
                 : "=r"(r[0]), "=r"(r[1]), "=r"(r[2]), "=r"(r[3]) : "r"(addr));
}
__device__ __forceinline__ void mma16816(float c[4], const unsigned a[4], const unsigned b[2]) {
    asm volatile(
        "mma.sync.aligned.m16n8k16.row.col.f32.f16.f16.f32 "
        "{%0,%1,%2,%3}, {%4,%5,%6,%7}, {%8,%9}, {%0,%1,%2,%3};\n"
        : "+f"(c[0]), "+f"(c[1]), "+f"(c[2]), "+f"(c[3])
        : "r"(a[0]), "r"(a[1]), "r"(a[2]), "r"(a[3]), "r"(b[0]), "r"(b[1]));
}

// ---------------- small kernels ----------------
__global__ void cvt_half_kernel(const float4* __restrict__ src, uint2* __restrict__ dst, int n4) {
    int i = blockIdx.x * 256 + threadIdx.x;
    if (i < n4) {
        float4 v = src[i];
        __half2 a = __floats2half2_rn(v.x, v.y);
        __half2 b = __floats2half2_rn(v.z, v.w);
        dst[i] = make_uint2(*(unsigned*)&a, *(unsigned*)&b);
    }
}

// router (one warp per token); per-block expert histogram -> g_pcnt (no global atomics)
__global__ __launch_bounds__(256) void router_kernel(
    const float* __restrict__ x, const float* __restrict__ Wr, const float* __restrict__ br)
{
    __shared__ int bc[NE];
    const int warp = (blockIdx.x * blockDim.x + threadIdx.x) >> 5;
    const int lane = threadIdx.x & 31;
    const int tid = threadIdx.x;
    if (tid < NE) bc[tid] = 0;
    __syncthreads();

    const float* xr = x + (size_t)warp * HIDDEN;
    float s[NE];
#pragma unroll
    for (int e = 0; e < NE; e++) s[e] = 0.f;

    for (int h = lane; h < HIDDEN; h += 32) {
        float xv = xr[h];
        const float4* w4 = reinterpret_cast<const float4*>(Wr + (size_t)h * NE);
        float4 wa = w4[0], wb = w4[1];
        s[0] += xv * wa.x; s[1] += xv * wa.y; s[2] += xv * wa.z; s[3] += xv * wa.w;
        s[4] += xv * wb.x; s[5] += xv * wb.y; s[6] += xv * wb.z; s[7] += xv * wb.w;
    }
#pragma unroll
    for (int e = 0; e < NE; e++)
#pragma unroll
        for (int o = 16; o > 0; o >>= 1) s[e] += __shfl_xor_sync(0xffffffffu, s[e], o);

    if (lane == 0) {
        float l[NE], m = -1e30f;
#pragma unroll
        for (int e = 0; e < NE; e++) { l[e] = s[e] + br[e]; m = fmaxf(m, l[e]); }
        float p[NE], Z = 0.f;
#pragma unroll
        for (int e = 0; e < NE; e++) { p[e] = expf(l[e] - m); Z += p[e]; }
#pragma unroll
        for (int e = 0; e < NE; e++) p[e] /= Z;

        int i1 = 0; float v1 = p[0];
#pragma unroll
        for (int e = 1; e < NE; e++) if (p[e] > v1) { v1 = p[e]; i1 = e; }
        int i2 = -1; float v2 = -1.f;
#pragma unroll
        for (int e = 0; e < NE; e++) if (e != i1 && p[e] > v2) { v2 = p[e]; i2 = e; }

        float ex = expf(v2 - v1);
        float w1 = 1.f / (1.f + ex);
        float w2 = ex / (1.f + ex);

        g_te[2 * warp + 0] = i1;  g_tw[2 * warp + 0] = w1;
        g_te[2 * warp + 1] = i2;  g_tw[2 * warp + 1] = w2;
        atomicAdd(&bc[i1], 1);
        atomicAdd(&bc[i2], 1);
    }
    __syncthreads();
    if (tid < NE) g_pcnt[blockIdx.x * NE + tid] = bc[tid];
}

// reduce partial counts -> g_cnt, g_off; zero g_fill
__global__ __launch_bounds__(256) void scan_kernel() {
    __shared__ int part[256];
    const int tid = threadIdx.x;
    for (int e = 0; e < NE; e++) {
        int sum = 0;
        for (int i = tid; i < NRBLK; i += 256) sum += g_pcnt[i * NE + e];
        part[tid] = sum;
        __syncthreads();
        for (int o = 128; o > 0; o >>= 1) {
            if (tid < o) part[tid] += part[tid + o];
            __syncthreads();
        }
        if (tid == 0) g_cnt[e] = part[0];
        __syncthreads();
    }
    if (tid == 0) {
        int acc = 0;
        for (int e = 0; e < NE; e++) { g_off[e] = acc; acc += g_cnt[e]; g_fill[e] = 0; }
    }
}

__global__ void scatter_kernel() {
    int t = blockIdx.x * 256 + threadIdx.x;
    if (t >= NTOK) return;
    int   e1 = g_te[2 * t],     e2 = g_te[2 * t + 1];
    float w1 = g_tw[2 * t],     w2 = g_tw[2 * t + 1];
    int s1 = atomicAdd(&g_fill[e1], 1);
    int p1 = g_off[e1] + s1;
    g_ent[p1] = (t << 1);       g_wt[p1] = w1;
    int s2 = atomicAdd(&g_fill[e2], 1);
    int p2 = g_off[e2] + s2;
    g_ent[p2] = (t << 1) | 1;   g_wt[p2] = w2;
}

// ---------------- GEMM1: h = gelu(gather(x) @ W1[e] + b1[e]) ----------------
__global__ __launch_bounds__(256, 1) void gemm1_kernel(const float* __restrict__ b1)
{
    const int e = blockIdx.z;
    const int rows = g_cnt[e];
    const int m0 = blockIdx.x * BM;
    if (m0 >= rows) return;
    const int off = g_off[e];
    const int n0 = blockIdx.y * BN;

    extern __shared__ __align__(128) char sa[];
    __shared__ int toks[BM];

    const int tid = threadIdx.x;
    const int wid = tid >> 5, lane = tid & 31;
    const int wm = (wid >> 2) * 64, wn = (wid & 3) * 64;

    if (tid < BM) {
        int r = m0 + tid;
        toks[tid] = (r < rows) ? (g_ent[off + r] >> 1) : -1;
    }
    __syncthreads();

    const __half* Wb = g_w1h + (size_t)e * HIDDEN * FFN;

#define LOAD1(ST, K0)                                                                    \
    do {                                                                                 \
        char* As_ = sa + (ST) * STAGE_B;                                                 \
        char* Bs_ = As_ + A_TILE_B;                                                      \
        _Pragma("unroll")                                                                \
        for (int i = 0; i < 2; i++) {                                                    \
            int f = tid + i * 256; int r = f >> 2, c = f & 3;                            \
            int tk = toks[r];                                                            \
            cpasync16(As_ + r * (ASTR * 2) + c * 16,                                     \
                      g_xh + (size_t)(tk < 0 ? 0 : tk) * HIDDEN + (K0) + c * 8,          \
                      tk >= 0);                                                          \
        }                                                                                \
        _Pragma("unroll")                                                                \
        for (int i = 0; i < 4; i++) {                                                    \
            int f = tid + i * 256; int r = f >> 5, c = f & 31;                           \
            cpasync16(Bs_ + r * (BSTR * 2) + c * 16,                                     \
                      Wb + (size_t)((K0) + r) * FFN + n0 + c * 8, true);                 \
        }                                                                                \
    } while (0)

    float c[4][8][4];
#pragma unroll
    for (int a = 0; a < 4; a++)
#pragma unroll
        for (int b = 0; b < 8; b++)
#pragma unroll
            for (int k = 0; k < 4; k++) c[a][b][k] = 0.f;

    const int KT = HIDDEN / BK;  // 32
    LOAD1(0, 0);        cpcommit();
    LOAD1(1, BK);       cpcommit();
    LOAD1(2, 2 * BK);   cpcommit();

    const int arow = (lane & 7) + ((lane >> 3) & 1) * 8;
    const int akoff = ((lane >> 4) & 1) * 8;
    const int brow_in = ((lane >> 3) & 1) * 8 + (lane & 7);
    const int bnoff = ((lane >> 4) & 1) * 8;

    for (int kt = 0; kt < KT; kt++) {
        cpwait<2>();
        __syncthreads();
        const int st = kt & (STAGES - 1);
        const char* As_ = sa + st * STAGE_B;
        const char* Bs_ = As_ + A_TILE_B;
        const unsigned abase = smem_u32(As_);
        const unsigned bbase = smem_u32(Bs_);
#pragma unroll
        for (int ks = 0; ks < 2; ks++) {
            const int k0h = ks * 16;
            unsigned afr[4][4];
#pragma unroll
            for (int mi = 0; mi < 4; mi++)
                ldsm4(afr[mi], abase + ((wm + mi * 16 + arow) * ASTR + k0h + akoff) * 2);
            unsigned bfr[8][2];
#pragma unroll
            for (int p = 0; p < 4; p++) {
                unsigned r4[4];
                ldsm4t(r4, bbase + ((k0h + brow_in) * BSTR + wn + p * 16 + bnoff) * 2);
                bfr[2 * p][0] = r4[0]; bfr[2 * p][1] = r4[1];
                bfr[2 * p + 1][0] = r4[2]; bfr[2 * p + 1][1] = r4[3];
            }
#pragma unroll
            for (int mi = 0; mi < 4; mi++)
#pragma unroll
                for (int ng = 0; ng < 8; ng++)
                    mma16816(c[mi][ng], afr[mi], bfr[ng]);
        }
        if (kt + 3 < KT) {
            int st2 = (kt + 3) & (STAGES - 1);
            LOAD1(st2, (kt + 3) * BK);
        }
        cpcommit();
    }
#undef LOAD1

    const float* b1e = b1 + (size_t)e * FFN;
#pragma unroll
    for (int mi = 0; mi < 4; mi++)
#pragma unroll
        for (int hh = 0; hh < 2; hh++) {
            int rl = wm + mi * 16 + (lane >> 2) + hh * 8;
            int r = m0 + rl;
            if (r < rows) {
                size_t base = (size_t)(off + r) * FFN + n0;
#pragma unroll
                for (int ng = 0; ng < 8; ng++) {
                    int col = wn + ng * 8 + 2 * (lane & 3);
                    float v0 = gelu_exact(c[mi][ng][hh * 2 + 0] + b1e[n0 + col]);
                    float v1 = gelu_exact(c[mi][ng][hh * 2 + 1] + b1e[n0 + col + 1]);
                    __half2 hv = __floats2half2_rn(v0, v1);
                    *reinterpret_cast<__half2*>(&g_h[base + col]) = hv;
                }
            }
        }
}

// ---------------- GEMM2: y[(token,k)] = w * (h @ W2[e] + b2[e])  (fp16 store) ----------------
__global__ __launch_bounds__(256, 1) void gemm2_kernel(const float* __restrict__ b2)
{
    const int e = blockIdx.z;
    const int rows = g_cnt[e];
    const int m0 = blockIdx.x * BM;
    if (m0 >= rows) return;
    const int off = g_off[e];
    const int n0 = blockIdx.y * BN;

    extern __shared__ __align__(128) char sa[];
    __shared__ int   ents[BM];
    __shared__ float wts[BM];

    const int tid = threadIdx.x;
    const int wid = tid >> 5, lane = tid & 31;
    const int wm = (wid >> 2) * 64, wn = (wid & 3) * 64;

    if (tid < BM) {
        int r = m0 + tid;
        ents[tid] = (r < rows) ? g_ent[off + r] : -1;
        wts [tid] = (r < rows) ? g_wt [off + r] : 0.f;
    }
    __syncthreads();

    const __half* Wb = g_w2h + (size_t)e * FFN * HIDDEN;

#define LOAD2(ST, K0)                                                                    \
    do {                                                                                 \
        char* As_ = sa + (ST) * STAGE_B;                                                 \
        char* Bs_ = As_ + A_TILE_B;                                                      \
        _Pragma("unroll")                                                                \
        for (int i = 0; i < 2; i++) {                                                    \
            int f = tid + i * 256; int r = f >> 2, c = f & 3;                            \
            bool valid = (m0 + r) < rows;                                                \
            cpasync16(As_ + r * (ASTR * 2) + c * 16,                                     \
                      g_h + (size_t)(valid ? (off + m0 + r) : 0) * FFN + (K0) + c * 8,   \
                      valid);                                                            \
        }                                                                                \
        _Pragma("unroll")                                                                \
        for (int i = 0; i < 4; i++) {                                                    \
            int f = tid + i * 256; int r = f >> 5, c = f & 31;                           \
            cpasync16(Bs_ + r * (BSTR * 2) + c * 16,                                     \
                      Wb + (size_t)((K0) + r) * HIDDEN + n0 + c * 8, true);              \
        }                                                                                \
    } while (0)

    float c[4][8][4];
#pragma unroll
    for (int a = 0; a < 4; a++)
#pragma unroll
        for (int b = 0; b < 8; b++)
#pragma unroll
            for (int k = 0; k < 4; k++) c[a][b][k] = 0.f;

    const int KT = FFN / BK;  // 64
    LOAD2(0, 0);        cpcommit();
    LOAD2(1, BK);       cpcommit();
    LOAD2(2, 2 * BK);   cpcommit();

    const int arow = (lane & 7) + ((lane >> 3) & 1) * 8;
    const int akoff = ((lane >> 4) & 1) * 8;
    const int brow_in = ((lane >> 3) & 1) * 8 + (lane & 7);
    const int bnoff = ((lane >> 4) & 1) * 8;

    for (int kt = 0; kt < KT; kt++) {
        cpwait<2>();
        __syncthreads();
        const int st = kt & (STAGES - 1);
        const char* As_ = sa + st * STAGE_B;
        const char* Bs_ = As_ + A_TILE_B;
        const unsigned abase = smem_u32(As_);
        const unsigned bbase = smem_u32(Bs_);
#pragma unroll
        for (int ks = 0; ks < 2; ks++) {
            const int k0h = ks * 16;
            unsigned afr[4][4];
#pragma unroll
            for (int mi = 0; mi < 4; mi++)
                ldsm4(afr[mi], abase + ((wm + mi * 16 + arow) * ASTR + k0h + akoff) * 2);
            unsigned bfr[8][2];
#pragma unroll
            for (int p = 0; p < 4; p++) {
                unsigned r4[4];
                ldsm4t(r4, bbase + ((k0h + brow_in) * BSTR + wn + p * 16 + bnoff) * 2);
                bfr[2 * p][0] = r4[0]; bfr[2 * p][1] = r4[1];
                bfr[2 * p + 1][0] = r4[2]; bfr[2 * p + 1][1] = r4[3];
            }
#pragma unroll
            for (int mi = 0; mi < 4; mi++)
#pragma unroll
                for (int ng = 0; ng < 8; ng++)
                    mma16816(c[mi][ng], afr[mi], bfr[ng]);
        }
        if (kt + 3 < KT) {
            int st2 = (kt + 3) & (STAGES - 1);
            LOAD2(st2, (kt + 3) * BK);
        }
        cpcommit();
    }
#undef LOAD2

    const float* b2e = b2 + (size_t)e * HIDDEN;
#pragma unroll
    for (int mi = 0; mi < 4; mi++)
#pragma unroll
        for (int hh = 0; hh < 2; hh++) {
            int rl = wm + mi * 16 + (lane >> 2) + hh * 8;
            int en = ents[rl];
            if (en >= 0) {
                int tok = en >> 1, kk = en & 1;
                float w = wts[rl];
                size_t base = ((size_t)tok * 2 + kk) * HIDDEN + n0;
#pragma unroll
                for (int ng = 0; ng < 8; ng++) {
                    int col = wn + ng * 8 + 2 * (lane & 3);
                    float v0 = w * (c[mi][ng][hh * 2 + 0] + b2e[n0 + col]);
                    float v1 = w * (c[mi][ng][hh * 2 + 1] + b2e[n0 + col + 1]);
                    *reinterpret_cast<__half2*>(&g_y[base + col]) = __floats2half2_rn(v0, v1);
                }
            }
        }
}

// ---------------- combine (fp16 y -> fp32 out) ----------------
__global__ void combine_kernel(float4* __restrict__ out) {
    int i = blockIdx.x * 256 + threadIdx.x;            // float4 index over out
    int t = i >> 8, cc = i & 255;                      // 256 float4 per token
    const uint2* y2 = reinterpret_cast<const uint2*>(g_y);   // 4 halfs per uint2
    uint2 pa = y2[((size_t)t * 2) * 256 + cc];
    uint2 pb = y2[((size_t)t * 2 + 1) * 256 + cc];
    __half2 a0 = *reinterpret_cast<__half2*>(&pa.x);
    __half2 a1 = *reinterpret_cast<__half2*>(&pa.y);
    __half2 b0 = *reinterpret_cast<__half2*>(&pb.x);
    __half2 b1 = *reinterpret_cast<__half2*>(&pb.y);
    float2 fa0 = __half22float2(a0), fa1 = __half22float2(a1);
    float2 fb0 = __half22float2(b0), fb1 = __half22float2(b1);
    out[i] = make_float4(fa0.x + fb0.x, fa0.y + fb0.y, fa1.x + fb1.x, fa1.y + fb1.y);
}

// ---------------- launch (graph has parallel branches via fork/join) ----------------
extern "C" void kernel_launch(void* const* d_in, const int* in_sizes, int n_in,
                              void* d_out, int out_size)
{
    const float* x  = (const float*)d_in[0];
    const float* Wr = (const float*)d_in[1];
    const float* br = (const float*)d_in[2];
    const float* W1 = (const float*)d_in[3];
    const float* b1 = (const float*)d_in[4];
    const float* W2 = (const float*)d_in[5];
    const float* b2 = (const float*)d_in[6];
    float* out = (float*)d_out;

    static cudaStream_t s1 = nullptr, s2 = nullptr;
    static cudaEvent_t evA = nullptr, ev1 = nullptr, ev2 = nullptr;
    if (s1 == nullptr) {
        cudaStreamCreateWithFlags(&s1, cudaStreamNonBlocking);
        cudaStreamCreateWithFlags(&s2, cudaStreamNonBlocking);
        cudaEventCreateWithFlags(&evA, cudaEventDisableTiming);
        cudaEventCreateWithFlags(&ev1, cudaEventDisableTiming);
        cudaEventCreateWithFlags(&ev2, cudaEventDisableTiming);
        cudaFuncSetAttribute(gemm1_kernel, cudaFuncAttributeMaxDynamicSharedMemorySize, SMEM_B);
        cudaFuncSetAttribute(gemm2_kernel, cudaFuncAttributeMaxDynamicSharedMemorySize, SMEM_B);
    }

    __half* xh_p  = nullptr; cudaGetSymbolAddress((void**)&xh_p,  g_xh);
    __half* w1h_p = nullptr; cudaGetSymbolAddress((void**)&w1h_p, g_w1h);
    __half* w2h_p = nullptr; cudaGetSymbolAddress((void**)&w2h_p, g_w2h);

    // fork side branches from the main (capturing) stream
    cudaEventRecord(evA, 0);
    cudaStreamWaitEvent(s1, evA, 0);
    cudaStreamWaitEvent(s2, evA, 0);

    // branch s1: x and W1 fp16 conversion (needed by gemm1)
    cvt_half_kernel<<<(NTOK * HIDDEN / 4) / 256, 256, 0, s1>>>(
        (const float4*)x, (uint2*)xh_p, NTOK * HIDDEN / 4);
    cvt_half_kernel<<<(NE * HIDDEN * FFN / 4) / 256, 256, 0, s1>>>(
        (const float4*)W1, (uint2*)w1h_p, NE * HIDDEN * FFN / 4);
    cudaEventRecord(ev1, s1);

    // branch s2: W2 conversion (needed only by gemm2; hides under router chain + gemm1)
    cvt_half_kernel<<<(NE * FFN * HIDDEN / 4) / 256, 256, 0, s2>>>(
        (const float4*)W2, (uint2*)w2h_p, NE * FFN * HIDDEN / 4);
    cudaEventRecord(ev2, s2);

    // main branch: routing chain (histogram router, no zero kernel)
    router_kernel<<<NRBLK, 256>>>(x, Wr, br);
    scan_kernel<<<1, 256>>>();
    scatter_kernel<<<NTOK / 256, 256>>>();

    // join s1 (x/W1 ready) then run gemm1
    cudaStreamWaitEvent(0, ev1, 0);
    gemm1_kernel<<<dim3(NTOK / BM, FFN / BN, NE), 256, SMEM_B>>>(b1);

    // join s2 (W2 ready) then gemm2 + combine
    cudaStreamWaitEvent(0, ev2, 0);
    gemm2_kernel<<<dim3(NTOK / BM, HIDDEN / BN, NE), 256, SMEM_B>>>(b2);
    combine_kernel<<<(NTOK * HIDDEN / 4) / 256, 256>>>(reinterpret_cast<float4*>(out));
}

// round 15
// speedup vs baseline: 1.0994x; 1.0153x over previous
#include <cuda_runtime.h>
#include <cuda_fp16.h>
#include <math.h>
#include <stdint.h>

#define HIDDEN 1024
#define FFN    2048
#define NE     8
#define NTOK   8192
#define TOTAL  (NTOK * 2)
#define TOK_PER_BLK 32                       // 8 warps x 4 tokens
#define NRBLK  (NTOK / TOK_PER_BLK)          // router blocks

#define BM 128
#define BN 256
#define BK 32
#define STAGES 4

#define ASTR 40                              // halfs per A smem row (80B)
#define BSTR 264                             // halfs per B smem row (528B)
#define A_TILE_B (BM * ASTR * 2)             // 10240
#define B_TILE_B (BK * BSTR * 2)             // 16896
#define STAGE_B  (A_TILE_B + B_TILE_B)       // 27136
#define SMEM_B   (STAGES * STAGE_B)          // 108544

// ---------------- device scratch ----------------
__device__ int    g_pcnt[NRBLK * NE];
__device__ int    g_cnt[NE];
__device__ int    g_off[NE];
__device__ int    g_fill[NE];
__device__ int    g_te[NTOK * 2];
__device__ float  g_tw[NTOK * 2];
__device__ int    g_ent[TOTAL];
__device__ float  g_wt [TOTAL];
__device__ __half g_xh [(size_t)NTOK * HIDDEN];        // fp16 x
__device__ __half g_w1h[(size_t)NE * HIDDEN * FFN];    // fp16 W1
__device__ __half g_w2h[(size_t)NE * FFN * HIDDEN];    // fp16 W2
__device__ __half g_h  [(size_t)TOTAL * FFN];          // fp16 gelu(xW1+b1)
__device__ __half g_y  [(size_t)NTOK * 2 * HIDDEN];    // fp16 per-(token,k) expert output

// ---------------- helpers ----------------
__device__ __forceinline__ float gelu_exact(float v) {
    return 0.5f * v * (1.0f + erff(v * 0.7071067811865476f));
}
__device__ __forceinline__ unsigned smem_u32(const void* p) {
    return (unsigned)__cvta_generic_to_shared(p);
}
__device__ __forceinline__ void cpasync16(void* smem, const void* g, bool valid) {
    unsigned s = smem_u32(smem);
    int sz = valid ? 16 : 0;
    asm volatile("cp.async.cg.shared.global [%0], [%1], 16, %2;\n" :: "r"(s), "l"(g), "r"(sz));
}
__device__ __forceinline__ void cpcommit() { asm volatile("cp.async.commit_group;\n"); }
template<int N> __device__ __forceinline__ void cpwait() {
    asm volatile("cp.async.wait_group %0;\n" :: "n"(N));
}
__device__ __forceinline__ void ldsm4(unsigned r[4], unsigned addr) {
    asm volatile("ldmatrix.sync.aligned.m8n8.x4.shared.b16 {%0,%1,%2,%3}, [%4];"
                 : "=r"(r[0]), "=r"(r[1]), "=r"(r[2]), "=r"(r[3]) : "r"(addr));
}
__device__ __forceinline__ void ldsm4t(unsigned r[4], unsigned addr) {
    asm volatile("ldmatrix.sync.aligned.m8n8.x4.trans.shared.b16 {%0,%1,%2,%3}, [%4];"
                 : "=r"(r[0]), "=r"(r[1]), "=r"(r[2]), "=r"(r[3]) : "r"(addr));
}
__device__ __forceinline__ void mma16816(float c[4], const unsigned a[4], const unsigned b[2]) {
    asm volatile(
        "mma.sync.aligned.m16n8k16.row.col.f32.f16.f16.f32 "
        "{%0,%1,%2,%3}, {%4,%5,%6,%7}, {%8,%9}, {%0,%1,%2,%3};\n"
        : "+f"(c[0]), "+f"(c[1]), "+f"(c[2]), "+f"(c[3])
        : "r"(a[0]), "r"(a[1]), "r"(a[2]), "r"(a[3]), "r"(b[0]), "r"(b[1]));
}

// ---------------- small kernels ----------------
__global__ void cvt_half_kernel(const float4* __restrict__ src, uint2* __restrict__ dst, int n4) {
    int i = blockIdx.x * 256 + threadIdx.x;
    if (i < n4) {
        float4 v = src[i];
        __half2 a = __floats2half2_rn(v.x, v.y);
        __half2 b = __floats2half2_rn(v.z, v.w);
        dst[i] = make_uint2(*(unsigned*)&a, *(unsigned*)&b);
    }
}

// router: each warp handles 4 tokens, Wr loads amortized 4x.
// Per-token FMA order identical to the 1-token/warp version (h = lane + i*32).
__global__ __launch_bounds__(256) void router_kernel(
    const float* __restrict__ x, const float* __restrict__ Wr, const float* __restrict__ br)
{
    __shared__ int bc[NE];
    const int tid = threadIdx.x;
    const int warp = (blockIdx.x * 256 + tid) >> 5;
    const int lane = tid & 31;
    const int t0 = warp * 4;
    if (tid < NE) bc[tid] = 0;
    __syncthreads();

    const float4* xr0 = reinterpret_cast<const float4*>(x + (size_t)(t0 + 0) * HIDDEN);
    const float4* xr1 = reinterpret_cast<const float4*>(x + (size_t)(t0 + 1) * HIDDEN);
    const float4* xr2 = reinterpret_cast<const float4*>(x + (size_t)(t0 + 2) * HIDDEN);
    const float4* xr3 = reinterpret_cast<const float4*>(x + (size_t)(t0 + 3) * HIDDEN);

    float s[4][NE];
#pragma unroll
    for (int tt = 0; tt < 4; tt++)
#pragma unroll
        for (int e = 0; e < NE; e++) s[tt][e] = 0.f;

#pragma unroll
    for (int i = 0; i < 8; i++) {
        int q = lane + i * 32;                         // float4 index; h0 = 4q
        const float4* w4 = reinterpret_cast<const float4*>(Wr + (size_t)(4 * q) * NE);
        float4 wa[4], wb[4];
#pragma unroll
        for (int j = 0; j < 4; j++) { wa[j] = w4[2 * j]; wb[j] = w4[2 * j + 1]; }

        float4 xv0 = xr0[q], xv1 = xr1[q], xv2 = xr2[q], xv3 = xr3[q];
#pragma unroll
        for (int j = 0; j < 4; j++) {
            float x0 = (j == 0) ? xv0.x : (j == 1) ? xv0.y : (j == 2) ? xv0.z : xv0.w;
            float x1 = (j == 0) ? xv1.x : (j == 1) ? xv1.y : (j == 2) ? xv1.z : xv1.w;
            float x2 = (j == 0) ? xv2.x : (j == 1) ? xv2.y : (j == 2) ? xv2.z : xv2.w;
            float x3 = (j == 0) ? xv3.x : (j == 1) ? xv3.y : (j == 2) ? xv3.z : xv3.w;
            s[0][0] += x0 * wa[j].x; s[0][1] += x0 * wa[j].y; s[0][2] += x0 * wa[j].z; s[0][3] += x0 * wa[j].w;
            s[0][4] += x0 * wb[j].x; s[0][5] += x0 * wb[j].y; s[0][6] += x0 * wb[j].z; s[0][7] += x0 * wb[j].w;
            s[1][0] += x1 * wa[j].x; s[1][1] += x1 * wa[j].y; s[1][2] += x1 * wa[j].z; s[1][3] += x1 * wa[j].w;
            s[1][4] += x1 * wb[j].x; s[1][5] += x1 * wb[j].y; s[1][6] += x1 * wb[j].z; s[1][7] += x1 * wb[j].w;
            s[2][0] += x2 * wa[j].x; s[2][1] += x2 * wa[j].y; s[2][2] += x2 * wa[j].z; s[2][3] += x2 * wa[j].w;
            s[2][4] += x2 * wb[j].x; s[2][5] += x2 * wb[j].y; s[2][6] += x2 * wb[j].z; s[2][7] += x2 * wb[j].w;
            s[3][0] += x3 * wa[j].x; s[3][1] += x3 * wa[j].y; s[3][2] += x3 * wa[j].z; s[3][3] += x3 * wa[j].w;
            s[3][4] += x3 * wb[j].x; s[3][5] += x3 * wb[j].y; s[3][6] += x3 * wb[j].z; s[3][7] += x3 * wb[j].w;
        }
    }
#pragma unroll
    for (int tt = 0; tt < 4; tt++)
#pragma unroll
        for (int e = 0; e < NE; e++)
#pragma unroll
            for (int o = 16; o > 0; o >>= 1)
                s[tt][e] += __shfl_xor_sync(0xffffffffu, s[tt][e], o);

    // lanes 0..3 each finish one token
    if (lane < 4) {
        const int tt = lane;
        const int tok = t0 + tt;
        float l[NE], m = -1e30f;
#pragma unroll
        for (int e = 0; e < NE; e++) { l[e] = s[tt][e] + br[e]; m = fmaxf(m, l[e]); }
        float p[NE], Z = 0.f;
#pragma unroll
        for (int e = 0; e < NE; e++) { p[e] = expf(l[e] - m); Z += p[e]; }
#pragma unroll
        for (int e = 0; e < NE; e++) p[e] /= Z;

        int i1 = 0; float v1 = p[0];
#pragma unroll
        for (int e = 1; e < NE; e++) if (p[e] > v1) { v1 = p[e]; i1 = e; }
        int i2 = -1; float v2 = -1.f;
#pragma unroll
        for (int e = 0; e < NE; e++) if (e != i1 && p[e] > v2) { v2 = p[e]; i2 = e; }

        float ex = expf(v2 - v1);
        float w1 = 1.f / (1.f + ex);
        float w2 = ex / (1.f + ex);

        g_te[2 * tok + 0] = i1;  g_tw[2 * tok + 0] = w1;
        g_te[2 * tok + 1] = i2;  g_tw[2 * tok + 1] = w2;
        atomicAdd(&bc[i1], 1);
        atomicAdd(&bc[i2], 1);
    }
    __syncthreads();
    if (tid < NE) g_pcnt[blockIdx.x * NE + tid] = bc[tid];
}

// reduce partial counts -> g_cnt, g_off; zero g_fill
__global__ __launch_bounds__(256) void scan_kernel() {
    __shared__ int part[256];
    const int tid = threadIdx.x;
    for (int e = 0; e < NE; e++) {
        int sum = 0;
        for (int i = tid; i < NRBLK; i += 256) sum += g_pcnt[i * NE + e];
        part[tid] = sum;
        __syncthreads();
        for (int o = 128; o > 0; o >>= 1) {
            if (tid < o) part[tid] += part[tid + o];
            __syncthreads();
        }
        if (tid == 0) g_cnt[e] = part[0];
        __syncthreads();
    }
    if (tid == 0) {
        int acc = 0;
        for (int e = 0; e < NE; e++) { g_off[e] = acc; acc += g_cnt[e]; g_fill[e] = 0; }
    }
}

__global__ void scatter_kernel() {
    int t = blockIdx.x * 256 + threadIdx.x;
    if (t >= NTOK) return;
    int   e1 = g_te[2 * t],     e2 = g_te[2 * t + 1];
    float w1 = g_tw[2 * t],     w2 = g_tw[2 * t + 1];
    int s1 = atomicAdd(&g_fill[e1], 1);
    int p1 = g_off[e1] + s1;
    g_ent[p1] = (t << 1);       g_wt[p1] = w1;
    int s2 = atomicAdd(&g_fill[e2], 1);
    int p2 = g_off[e2] + s2;
    g_ent[p2] = (t << 1) | 1;   g_wt[p2] = w2;
}

// ---------------- GEMM1: h = gelu(gather(x) @ W1[e] + b1[e]) ----------------
__global__ __launch_bounds__(256, 1) void gemm1_kernel(const float* __restrict__ b1)
{
    const int e = blockIdx.z;
    const int rows = g_cnt[e];
    const int m0 = blockIdx.x * BM;
    if (m0 >= rows) return;
    const int off = g_off[e];
    const int n0 = blockIdx.y * BN;

    extern __shared__ __align__(128) char sa[];
    __shared__ int toks[BM];

    const int tid = threadIdx.x;
    const int wid = tid >> 5, lane = tid & 31;
    const int wm = (wid >> 2) * 64, wn = (wid & 3) * 64;

    if (tid < BM) {
        int r = m0 + tid;
        toks[tid] = (r < rows) ? (g_ent[off + r] >> 1) : -1;
    }
    __syncthreads();

    const __half* Wb = g_w1h + (size_t)e * HIDDEN * FFN;

#define LOAD1(ST, K0)                                                                    \
    do {                                                                                 \
        char* As_ = sa + (ST) * STAGE_B;                                                 \
        char* Bs_ = As_ + A_TILE_B;                                                      \
        _Pragma("unroll")                                                                \
        for (int i = 0; i < 2; i++) {                                                    \
            int f = tid + i * 256; int r = f >> 2, c = f & 3;                            \
            int tk = toks[r];                                                            \
            cpasync16(As_ + r * (ASTR * 2) + c * 16,                                     \
                      g_xh + (size_t)(tk < 0 ? 0 : tk) * HIDDEN + (K0) + c * 8,          \
                      tk >= 0);                                                          \
        }                                                                                \
        _Pragma("unroll")                                                                \
        for (int i = 0; i < 4; i++) {                                                    \
            int f = tid + i * 256; int r = f >> 5, c = f & 31;                           \
            cpasync16(Bs_ + r * (BSTR * 2) + c * 16,                                     \
                      Wb + (size_t)((K0) + r) * FFN + n0 + c * 8, true);                 \
        }                                                                                \
    } while (0)

    float c[4][8][4];
#pragma unroll
    for (int a = 0; a < 4; a++)
#pragma unroll
        for (int b = 0; b < 8; b++)
#pragma unroll
            for (int k = 0; k < 4; k++) c[a][b][k] = 0.f;

    const int KT = HIDDEN / BK;  // 32
    LOAD1(0, 0);        cpcommit();
    LOAD1(1, BK);       cpcommit();
    LOAD1(2, 2 * BK);   cpcommit();

    const int arow = (lane & 7) + ((lane >> 3) & 1) * 8;
    const int akoff = ((lane >> 4) & 1) * 8;
    const int brow_in = ((lane >> 3) & 1) * 8 + (lane & 7);
    const int bnoff = ((lane >> 4) & 1) * 8;

    for (int kt = 0; kt < KT; kt++) {
        cpwait<2>();
        __syncthreads();
        const int st = kt & (STAGES - 1);
        const char* As_ = sa + st * STAGE_B;
        const char* Bs_ = As_ + A_TILE_B;
        const unsigned abase = smem_u32(As_);
        const unsigned bbase = smem_u32(Bs_);
#pragma unroll
        for (int ks = 0; ks < 2; ks++) {
            const int k0h = ks * 16;
            unsigned afr[4][4];
#pragma unroll
            for (int mi = 0; mi < 4; mi++)
                ldsm4(afr[mi], abase + ((wm + mi * 16 + arow) * ASTR + k0h + akoff) * 2);
            unsigned bfr[8][2];
#pragma unroll
            for (int p = 0; p < 4; p++) {
                unsigned r4[4];
                ldsm4t(r4, bbase + ((k0h + brow_in) * BSTR + wn + p * 16 + bnoff) * 2);
                bfr[2 * p][0] = r4[0]; bfr[2 * p][1] = r4[1];
                bfr[2 * p + 1][0] = r4[2]; bfr[2 * p + 1][1] = r4[3];
            }
#pragma unroll
            for (int mi = 0; mi < 4; mi++)
#pragma unroll
                for (int ng = 0; ng < 8; ng++)
                    mma16816(c[mi][ng], afr[mi], bfr[ng]);
        }
        if (kt + 3 < KT) {
            int st2 = (kt + 3) & (STAGES - 1);
            LOAD1(st2, (kt + 3) * BK);
        }
        cpcommit();
    }
#undef LOAD1

    const float* b1e = b1 + (size_t)e * FFN;
#pragma unroll
    for (int mi = 0; mi < 4; mi++)
#pragma unroll
        for (int hh = 0; hh < 2; hh++) {
            int rl = wm + mi * 16 + (lane >> 2) + hh * 8;
            int r = m0 + rl;
            if (r < rows) {
                size_t base = (size_t)(off + r) * FFN + n0;
#pragma unroll
                for (int ng = 0; ng < 8; ng++) {
                    int col = wn + ng * 8 + 2 * (lane & 3);
                    float v0 = gelu_exact(c[mi][ng][hh * 2 + 0] + b1e[n0 + col]);
                    float v1 = gelu_exact(c[mi][ng][hh * 2 + 1] + b1e[n0 + col + 1]);
                    __half2 hv = __floats2half2_rn(v0, v1);
                    *reinterpret_cast<__half2*>(&g_h[base + col]) = hv;
                }
            }
        }
}

// ---------------- GEMM2: y[(token,k)] = w * (h @ W2[e] + b2[e])  (fp16 store) ----------------
__global__ __launch_bounds__(256, 1) void gemm2_kernel(const float* __restrict__ b2)
{
    const int e = blockIdx.z;
    const int rows = g_cnt[e];
    const int m0 = blockIdx.x * BM;
    if (m0 >= rows) return;
    const int off = g_off[e];
    const int n0 = blockIdx.y * BN;

    extern __shared__ __align__(128) char sa[];
    __shared__ int   ents[BM];
    __shared__ float wts[BM];

    const int tid = threadIdx.x;
    const int wid = tid >> 5, lane = tid & 31;
    const int wm = (wid >> 2) * 64, wn = (wid & 3) * 64;

    if (tid < BM) {
        int r = m0 + tid;
        ents[tid] = (r < rows) ? g_ent[off + r] : -1;
        wts [tid] = (r < rows) ? g_wt [off + r] : 0.f;
    }
    __syncthreads();

    const __half* Wb = g_w2h + (size_t)e * FFN * HIDDEN;

#define LOAD2(ST, K0)                                                                    \
    do {                                                                                 \
        char* As_ = sa + (ST) * STAGE_B;                                                 \
        char* Bs_ = As_ + A_TILE_B;                                                      \
        _Pragma("unroll")                                                                \
        for (int i = 0; i < 2; i++) {                                                    \
            int f = tid + i * 256; int r = f >> 2, c = f & 3;                            \
            bool valid = (m0 + r) < rows;                                                \
            cpasync16(As_ + r * (ASTR * 2) + c * 16,                                     \
                      g_h + (size_t)(valid ? (off + m0 + r) : 0) * FFN + (K0) + c * 8,   \
                      valid);                                                            \
        }                                                                                \
        _Pragma("unroll")                                                                \
        for (int i = 0; i < 4; i++) {                                                    \
            int f = tid + i * 256; int r = f >> 5, c = f & 31;                           \
            cpasync16(Bs_ + r * (BSTR * 2) + c * 16,                                     \
                      Wb + (size_t)((K0) + r) * HIDDEN + n0 + c * 8, true);              \
        }                                                                                \
    } while (0)

    float c[4][8][4];
#pragma unroll
    for (int a = 0; a < 4; a++)
#pragma unroll
        for (int b = 0; b < 8; b++)
#pragma unroll
            for (int k = 0; k < 4; k++) c[a][b][k] = 0.f;

    const int KT = FFN / BK;  // 64
    LOAD2(0, 0);        cpcommit();
    LOAD2(1, BK);       cpcommit();
    LOAD2(2, 2 * BK);   cpcommit();

    const int arow = (lane & 7) + ((lane >> 3) & 1) * 8;
    const int akoff = ((lane >> 4) & 1) * 8;
    const int brow_in = ((lane >> 3) & 1) * 8 + (lane & 7);
    const int bnoff = ((lane >> 4) & 1) * 8;

    for (int kt = 0; kt < KT; kt++) {
        cpwait<2>();
        __syncthreads();
        const int st = kt & (STAGES - 1);
        const char* As_ = sa + st * STAGE_B;
        const char* Bs_ = As_ + A_TILE_B;
        const unsigned abase = smem_u32(As_);
        const unsigned bbase = smem_u32(Bs_);
#pragma unroll
        for (int ks = 0; ks < 2; ks++) {
            const int k0h = ks * 16;
            unsigned afr[4][4];
#pragma unroll
            for (int mi = 0; mi < 4; mi++)
                ldsm4(afr[mi], abase + ((wm + mi * 16 + arow) * ASTR + k0h + akoff) * 2);
            unsigned bfr[8][2];
#pragma unroll
            for (int p = 0; p < 4; p++) {
                unsigned r4[4];
                ldsm4t(r4, bbase + ((k0h + brow_in) * BSTR + wn + p * 16 + bnoff) * 2);
                bfr[2 * p][0] = r4[0]; bfr[2 * p][1] = r4[1];
                bfr[2 * p + 1][0] = r4[2]; bfr[2 * p + 1][1] = r4[3];
            }
#pragma unroll
            for (int mi = 0; mi < 4; mi++)
#pragma unroll
                for (int ng = 0; ng < 8; ng++)
                    mma16816(c[mi][ng], afr[mi], bfr[ng]);
        }
        if (kt + 3 < KT) {
            int st2 = (kt + 3) & (STAGES - 1);
            LOAD2(st2, (kt + 3) * BK);
        }
        cpcommit();
    }
#undef LOAD2

    const float* b2e = b2 + (size_t)e * HIDDEN;
#pragma unroll
    for (int mi = 0; mi < 4; mi++)
#pragma unroll
        for (int hh = 0; hh < 2; hh++) {
            int rl = wm + mi * 16 + (lane >> 2) + hh * 8;
            int en = ents[rl];
            if (en >= 0) {
                int tok = en >> 1, kk = en & 1;
                float w = wts[rl];
                size_t base = ((size_t)tok * 2 + kk) * HIDDEN + n0;
#pragma unroll
                for (int ng = 0; ng < 8; ng++) {
                    int col = wn + ng * 8 + 2 * (lane & 3);
                    float v0 = w * (c[mi][ng][hh * 2 + 0] + b2e[n0 + col]);
                    float v1 = w * (c[mi][ng][hh * 2 + 1] + b2e[n0 + col + 1]);
                    *reinterpret_cast<__half2*>(&g_y[base + col]) = __floats2half2_rn(v0, v1);
                }
            }
        }
}

// ---------------- combine (fp16 y -> fp32 out) ----------------
__global__ void combine_kernel(float4* __restrict__ out) {
    int i = blockIdx.x * 256 + threadIdx.x;            // float4 index over out
    int t = i >> 8, cc = i & 255;                      // 256 float4 per token
    const uint2* y2 = reinterpret_cast<const uint2*>(g_y);   // 4 halfs per uint2
    uint2 pa = y2[((size_t)t * 2) * 256 + cc];
    uint2 pb = y2[((size_t)t * 2 + 1) * 256 + cc];
    __half2 a0 = *reinterpret_cast<__half2*>(&pa.x);
    __half2 a1 = *reinterpret_cast<__half2*>(&pa.y);
    __half2 b0 = *reinterpret_cast<__half2*>(&pb.x);
    __half2 b1 = *reinterpret_cast<__half2*>(&pb.y);
    float2 fa0 = __half22float2(a0), fa1 = __half22float2(a1);
    float2 fb0 = __half22float2(b0), fb1 = __half22float2(b1);
    out[i] = make_float4(fa0.x + fb0.x, fa0.y + fb0.y, fa1.x + fb1.x, fa1.y + fb1.y);
}

// ---------------- launch (graph has parallel branches via fork/join) ----------------
extern "C" void kernel_launch(void* const* d_in, const int* in_sizes, int n_in,
                              void* d_out, int out_size)
{
    const float* x  = (const float*)d_in[0];
    const float* Wr = (const float*)d_in[1];
    const float* br = (const float*)d_in[2];
    const float* W1 = (const float*)d_in[3];
    const float* b1 = (const float*)d_in[4];
    const float* W2 = (const float*)d_in[5];
    const float* b2 = (const float*)d_in[6];
    float* out = (float*)d_out;

    static cudaStream_t s1 = nullptr, s2 = nullptr;
    static cudaEvent_t evA = nullptr, ev1 = nullptr, ev2 = nullptr;
    if (s1 == nullptr) {
        cudaStreamCreateWithFlags(&s1, cudaStreamNonBlocking);
        cudaStreamCreateWithFlags(&s2, cudaStreamNonBlocking);
        cudaEventCreateWithFlags(&evA, cudaEventDisableTiming);
        cudaEventCreateWithFlags(&ev1, cudaEventDisableTiming);
        cudaEventCreateWithFlags(&ev2, cudaEventDisableTiming);
        cudaFuncSetAttribute(gemm1_kernel, cudaFuncAttributeMaxDynamicSharedMemorySize, SMEM_B);
        cudaFuncSetAttribute(gemm2_kernel, cudaFuncAttributeMaxDynamicSharedMemorySize, SMEM_B);
    }

    __half* xh_p  = nullptr; cudaGetSymbolAddress((void**)&xh_p,  g_xh);
    __half* w1h_p = nullptr; cudaGetSymbolAddress((void**)&w1h_p, g_w1h);
    __half* w2h_p = nullptr; cudaGetSymbolAddress((void**)&w2h_p, g_w2h);

    // fork side branches from the main (capturing) stream
    cudaEventRecord(evA, 0);
    cudaStreamWaitEvent(s1, evA, 0);
    cudaStreamWaitEvent(s2, evA, 0);

    // branch s1: x and W1 fp16 conversion (needed by gemm1)
    cvt_half_kernel<<<(NTOK * HIDDEN / 4) / 256, 256, 0, s1>>>(
        (const float4*)x, (uint2*)xh_p, NTOK * HIDDEN / 4);
    cvt_half_kernel<<<(NE * HIDDEN * FFN / 4) / 256, 256, 0, s1>>>(
        (const float4*)W1, (uint2*)w1h_p, NE * HIDDEN * FFN / 4);
    cudaEventRecord(ev1, s1);

    // branch s2: W2 conversion (needed only by gemm2; hides under router chain + gemm1)
    cvt_half_kernel<<<(NE * FFN * HIDDEN / 4) / 256, 256, 0, s2>>>(
        (const float4*)W2, (uint2*)w2h_p, NE * FFN * HIDDEN / 4);
    cudaEventRecord(ev2, s2);

    // main branch: routing chain (4-token/warp router, histogram counting)
    router_kernel<<<NRBLK, 256>>>(x, Wr, br);
    scan_kernel<<<1, 256>>>();
    scatter_kernel<<<NTOK / 256, 256>>>();

    // join s1 (x/W1 ready) then run gemm1
    cudaStreamWaitEvent(0, ev1, 0);
    gemm1_kernel<<<dim3(NTOK / BM, FFN / BN, NE), 256, SMEM_B>>>(b1);

    // join s2 (W2 ready) then gemm2 + combine
    cudaStreamWaitEvent(0, ev2, 0);
    gemm2_kernel<<<dim3(NTOK / BM, HIDDEN / BN, NE), 256, SMEM_B>>>(b2);
    combine_kernel<<<(NTOK * HIDDEN / 4) / 256, 256>>>(reinterpret_cast<float4*>(out));
}